// round 2
// baseline (speedup 1.0000x reference)
#include <cuda_runtime.h>
#include <cuda_bf16.h>
#include <cstdint>

// Problem constants
#define NRES 384
#define CZ   128
#define NH   4
#define CH   32
#define HC   128              // NH*CH
#define RTOT (NRES*NRES)      // 147456
#define LN_EPS 1e-5f
#define Q_SCALE 0.17677669529663687f   // 1/sqrt(32)

// Scratch (device globals — no runtime allocation allowed)
__device__ float g_zn [RTOT * CZ];
__device__ float g_q  [RTOT * HC];
__device__ float g_k  [RTOT * HC];
__device__ float g_v  [RTOT * HC];
__device__ float g_g  [RTOT * HC];   // sigmoid gate
__device__ float g_tri[NH * RTOT];   // tri bias [h, x, y]
__device__ float g_o  [RTOT * HC];   // gated attention output

// ---------------------------------------------------------------------------
// 1. LayerNorm: one warp per row of 128 channels (float4 per lane)
// ---------------------------------------------------------------------------
__global__ __launch_bounds__(256) void ln_kernel(const float* __restrict__ z,
                                                 const float* __restrict__ gamma,
                                                 const float* __restrict__ beta) {
    int row  = blockIdx.x * 8 + (threadIdx.x >> 5);
    int lane = threadIdx.x & 31;
    const float4* zp = reinterpret_cast<const float4*>(z + (size_t)row * CZ);
    float4 x = zp[lane];
    float s  = x.x + x.y + x.z + x.w;
    float ss = x.x*x.x + x.y*x.y + x.z*x.z + x.w*x.w;
    #pragma unroll
    for (int o = 16; o; o >>= 1) {
        s  += __shfl_xor_sync(0xffffffffu, s,  o);
        ss += __shfl_xor_sync(0xffffffffu, ss, o);
    }
    float mean = s * (1.0f / CZ);
    float var  = ss * (1.0f / CZ) - mean * mean;
    float rstd = rsqrtf(var + LN_EPS);
    float4 gm = reinterpret_cast<const float4*>(gamma)[lane];
    float4 bt = reinterpret_cast<const float4*>(beta)[lane];
    float4 o4;
    o4.x = (x.x - mean) * rstd * gm.x + bt.x;
    o4.y = (x.y - mean) * rstd * gm.y + bt.y;
    o4.z = (x.z - mean) * rstd * gm.z + bt.z;
    o4.w = (x.w - mean) * rstd * gm.w + bt.w;
    reinterpret_cast<float4*>(g_zn + (size_t)row * CZ)[lane] = o4;
}

// ---------------------------------------------------------------------------
// 2. Projection GEMM: zn[147456,128] @ {w_q,w_k,w_v,w_g}[128,128]
//    64x64 block tile, BK=16, 256 threads, 4x4 micro tile.
//    grid = (RTOT/64, 8); blockIdx.y picks 64-col slab of the 512 output cols.
// ---------------------------------------------------------------------------
__global__ __launch_bounds__(256) void proj_kernel(const float* __restrict__ wq,
                                                   const float* __restrict__ wk,
                                                   const float* __restrict__ wv,
                                                   const float* __restrict__ wg,
                                                   const float* __restrict__ bg) {
    __shared__ float As[16][64];
    __shared__ float Bs[16][64];

    const int r0 = blockIdx.x * 64;
    const int c0 = blockIdx.y * 64;            // global col 0..511
    const int which = c0 >> 7;                 // 0:q 1:k 2:v 3:g
    const int n0 = c0 & 127;
    const float* W = (which == 0) ? wq : (which == 1) ? wk : (which == 2) ? wv : wg;

    const int tid = threadIdx.x;
    const int tm = tid >> 4, tn = tid & 15;    // 16x16 thread grid
    const int a_row = tid >> 2;                // 0..63
    const int a_kg  = (tid & 3) * 4;           // 0,4,8,12
    const int b_k   = tid >> 4;                // 0..15
    const int b_ng  = (tid & 15) * 4;          // 0..60

    float acc[4][4];
    #pragma unroll
    for (int i = 0; i < 4; i++)
        #pragma unroll
        for (int j = 0; j < 4; j++) acc[i][j] = 0.f;

    for (int k0 = 0; k0 < CZ; k0 += 16) {
        float4 av = *reinterpret_cast<const float4*>(
            g_zn + (size_t)(r0 + a_row) * CZ + k0 + a_kg);
        As[a_kg + 0][a_row] = av.x;
        As[a_kg + 1][a_row] = av.y;
        As[a_kg + 2][a_row] = av.z;
        As[a_kg + 3][a_row] = av.w;
        float4 bv = *reinterpret_cast<const float4*>(W + (size_t)(k0 + b_k) * HC + n0 + b_ng);
        *reinterpret_cast<float4*>(&Bs[b_k][b_ng]) = bv;
        __syncthreads();
        #pragma unroll
        for (int kk = 0; kk < 16; kk++) {
            float4 a4 = *reinterpret_cast<const float4*>(&As[kk][tm * 4]);
            float4 b4 = *reinterpret_cast<const float4*>(&Bs[kk][tn * 4]);
            float aa[4] = {a4.x, a4.y, a4.z, a4.w};
            float bb[4] = {b4.x, b4.y, b4.z, b4.w};
            #pragma unroll
            for (int i = 0; i < 4; i++)
                #pragma unroll
                for (int j = 0; j < 4; j++) acc[i][j] = fmaf(aa[i], bb[j], acc[i][j]);
        }
        __syncthreads();
    }

    #pragma unroll
    for (int i = 0; i < 4; i++) {
        int r = r0 + tm * 4 + i;
        #pragma unroll
        for (int j = 0; j < 4; j++) {
            int c  = c0 + tn * 4 + j;          // 0..511
            int lc = c & 127;
            float v = acc[i][j];
            size_t idx = (size_t)r * HC + lc;
            if (c < 128)       g_q[idx] = v * Q_SCALE;
            else if (c < 256)  g_k[idx] = v;
            else if (c < 384)  g_v[idx] = v;
            else               g_g[idx] = 1.f / (1.f + __expf(-(v + bg[lc])));
        }
    }
}

// ---------------------------------------------------------------------------
// 3. Tri-bias: tri[h, r] = dot(zn[r], w_bias[:, h]).  One warp per row.
// ---------------------------------------------------------------------------
__global__ __launch_bounds__(256) void tri_kernel(const float* __restrict__ wb) {
    int row  = blockIdx.x * 8 + (threadIdx.x >> 5);
    int lane = threadIdx.x & 31;
    float4 zv = reinterpret_cast<const float4*>(g_zn + (size_t)row * CZ)[lane];
    float zz[4] = {zv.x, zv.y, zv.z, zv.w};
    float acc[NH] = {0.f, 0.f, 0.f, 0.f};
    int c = lane * 4;
    #pragma unroll
    for (int t = 0; t < 4; t++)
        #pragma unroll
        for (int h = 0; h < NH; h++) acc[h] = fmaf(zz[t], wb[(c + t) * NH + h], acc[h]);
    #pragma unroll
    for (int o = 16; o; o >>= 1)
        #pragma unroll
        for (int h = 0; h < NH; h++) acc[h] += __shfl_xor_sync(0xffffffffu, acc[h], o);
    if (lane == 0) {
        #pragma unroll
        for (int h = 0; h < NH; h++) g_tri[(size_t)h * RTOT + row] = acc[h];
    }
}

// ---------------------------------------------------------------------------
// 4. Attention: one block per (i, h). 384 threads, one query row j each.
//    K/V for this (i,h) staged in dynamic smem; online softmax; gate fused.
// ---------------------------------------------------------------------------
#define SMEM_ATTN ((NRES*CH*2 + NRES) * 4)
__global__ __launch_bounds__(NRES) void attn_kernel(const float* __restrict__ mask) {
    extern __shared__ float sm[];
    float* ks = sm;
    float* vs = sm + NRES * CH;
    float* mb = sm + 2 * NRES * CH;

    const int i = blockIdx.x;
    const int h = blockIdx.y;
    const int tid = threadIdx.x;
    const size_t rowbase = (size_t)i * NRES;

    // cooperative K/V load: 8 threads per row, 48 rows per pass
    #pragma unroll
    for (int p = 0; p < 8; p++) {
        int rr = p * 48 + (tid >> 3);
        int c4 = (tid & 7) * 4;
        size_t gidx = (rowbase + rr) * HC + h * CH + c4;
        *reinterpret_cast<float4*>(&ks[rr * CH + c4]) =
            *reinterpret_cast<const float4*>(&g_k[gidx]);
        *reinterpret_cast<float4*>(&vs[rr * CH + c4]) =
            *reinterpret_cast<const float4*>(&g_v[gidx]);
    }
    mb[tid] = 1.0e9f * (mask[rowbase + tid] - 1.f);
    __syncthreads();

    const int j = tid;
    float4 q4[8];
    size_t qbase = (rowbase + j) * HC + h * CH;
    #pragma unroll
    for (int t = 0; t < 8; t++)
        q4[t] = *reinterpret_cast<const float4*>(&g_q[qbase + t * 4]);
    const float* tri_row = g_tri + (size_t)h * RTOT + (size_t)j * NRES;

    float m = -1.0e30f, l = 0.f;
    float acc[CH];
    #pragma unroll
    for (int d = 0; d < CH; d++) acc[d] = 0.f;

    for (int kk = 0; kk < NRES; kk++) {
        float s = tri_row[kk] + mb[kk];
        const float4* krow = reinterpret_cast<const float4*>(&ks[kk * CH]);
        #pragma unroll
        for (int t = 0; t < 8; t++) {
            float4 kv = krow[t];
            s = fmaf(q4[t].x, kv.x, s);
            s = fmaf(q4[t].y, kv.y, s);
            s = fmaf(q4[t].z, kv.z, s);
            s = fmaf(q4[t].w, kv.w, s);
        }
        const float4* vrow = reinterpret_cast<const float4*>(&vs[kk * CH]);
        if (s <= m) {
            float p = __expf(s - m);
            l += p;
            #pragma unroll
            for (int t = 0; t < 8; t++) {
                float4 vv = vrow[t];
                acc[t*4+0] = fmaf(p, vv.x, acc[t*4+0]);
                acc[t*4+1] = fmaf(p, vv.y, acc[t*4+1]);
                acc[t*4+2] = fmaf(p, vv.z, acc[t*4+2]);
                acc[t*4+3] = fmaf(p, vv.w, acc[t*4+3]);
            }
        } else {
            float cf = __expf(m - s);
            m = s;
            l = l * cf + 1.f;
            #pragma unroll
            for (int t = 0; t < 8; t++) {
                float4 vv = vrow[t];
                acc[t*4+0] = fmaf(acc[t*4+0], cf, vv.x);
                acc[t*4+1] = fmaf(acc[t*4+1], cf, vv.y);
                acc[t*4+2] = fmaf(acc[t*4+2], cf, vv.z);
                acc[t*4+3] = fmaf(acc[t*4+3], cf, vv.w);
            }
        }
    }

    float inv = 1.f / l;
    size_t obase = (rowbase + j) * HC + h * CH;
    #pragma unroll
    for (int t = 0; t < 8; t++) {
        float4 gg = *reinterpret_cast<const float4*>(&g_g[obase + t * 4]);
        float4 o4;
        o4.x = acc[t*4+0] * inv * gg.x;
        o4.y = acc[t*4+1] * inv * gg.y;
        o4.z = acc[t*4+2] * inv * gg.z;
        o4.w = acc[t*4+3] * inv * gg.w;
        *reinterpret_cast<float4*>(&g_o[obase + t * 4]) = o4;
    }
}

// ---------------------------------------------------------------------------
// 5. Output GEMM: g_o[147456,128] @ w_o[128,128] + b_o -> out
// ---------------------------------------------------------------------------
__global__ __launch_bounds__(256) void out_kernel(const float* __restrict__ wo,
                                                  const float* __restrict__ bo,
                                                  float* __restrict__ out) {
    __shared__ float As[16][64];
    __shared__ float Bs[16][64];

    const int r0 = blockIdx.x * 64;
    const int n0 = blockIdx.y * 64;
    const int tid = threadIdx.x;
    const int tm = tid >> 4, tn = tid & 15;
    const int a_row = tid >> 2;
    const int a_kg  = (tid & 3) * 4;
    const int b_k   = tid >> 4;
    const int b_ng  = (tid & 15) * 4;

    float acc[4][4];
    #pragma unroll
    for (int i = 0; i < 4; i++)
        #pragma unroll
        for (int j = 0; j < 4; j++) acc[i][j] = 0.f;

    for (int k0 = 0; k0 < HC; k0 += 16) {
        float4 av = *reinterpret_cast<const float4*>(
            g_o + (size_t)(r0 + a_row) * HC + k0 + a_kg);
        As[a_kg + 0][a_row] = av.x;
        As[a_kg + 1][a_row] = av.y;
        As[a_kg + 2][a_row] = av.z;
        As[a_kg + 3][a_row] = av.w;
        float4 bv = *reinterpret_cast<const float4*>(wo + (size_t)(k0 + b_k) * CZ + n0 + b_ng);
        *reinterpret_cast<float4*>(&Bs[b_k][b_ng]) = bv;
        __syncthreads();
        #pragma unroll
        for (int kk = 0; kk < 16; kk++) {
            float4 a4 = *reinterpret_cast<const float4*>(&As[kk][tm * 4]);
            float4 b4 = *reinterpret_cast<const float4*>(&Bs[kk][tn * 4]);
            float aa[4] = {a4.x, a4.y, a4.z, a4.w};
            float bb[4] = {b4.x, b4.y, b4.z, b4.w};
            #pragma unroll
            for (int i = 0; i < 4; i++)
                #pragma unroll
                for (int j = 0; j < 4; j++) acc[i][j] = fmaf(aa[i], bb[j], acc[i][j]);
        }
        __syncthreads();
    }

    #pragma unroll
    for (int i = 0; i < 4; i++) {
        int r = r0 + tm * 4 + i;
        #pragma unroll
        for (int j = 0; j < 4; j++) {
            int c = n0 + tn * 4 + j;
            out[(size_t)r * CZ + c] = acc[i][j] + bo[c];
        }
    }
}

// ---------------------------------------------------------------------------
extern "C" void kernel_launch(void* const* d_in, const int* in_sizes, int n_in,
                              void* d_out, int out_size) {
    const float* z      = (const float*)d_in[0];
    const float* mask   = (const float*)d_in[1];
    const float* gamma  = (const float*)d_in[2];
    const float* beta   = (const float*)d_in[3];
    const float* w_bias = (const float*)d_in[4];
    const float* w_q    = (const float*)d_in[5];
    const float* w_k    = (const float*)d_in[6];
    const float* w_v    = (const float*)d_in[7];
    const float* w_g    = (const float*)d_in[8];
    const float* b_g    = (const float*)d_in[9];
    const float* w_o    = (const float*)d_in[10];
    const float* b_o    = (const float*)d_in[11];
    float* out = (float*)d_out;

    cudaFuncSetAttribute(attn_kernel, cudaFuncAttributeMaxDynamicSharedMemorySize, SMEM_ATTN);

    ln_kernel<<<RTOT / 8, 256>>>(z, gamma, beta);
    proj_kernel<<<dim3(RTOT / 64, 8), 256>>>(w_q, w_k, w_v, w_g, b_g);
    tri_kernel<<<RTOT / 8, 256>>>(w_bias);
    attn_kernel<<<dim3(NRES, NH), NRES, SMEM_ATTN>>>(mask);
    out_kernel<<<dim3(RTOT / 64, 2), 256>>>(w_o, b_o, out);
}